// round 1
// baseline (speedup 1.0000x reference)
#include <cuda_runtime.h>

#define DIM 80
#define DD 6400
#define D3 512000
#define NPTS 200000

// Scratch feature maps (device globals — no allocation in kernel_launch)
__device__ float g_f1[64 * D3];
__device__ float g_f2[64 * D3];

// ---------------------------------------------------------------------------
// 3D conv 3x3x3, zero pad 1, + bias + ReLU.
// Block: 64 out channels x (4z,4y,8x) spatial tile. 256 threads.
// Thread: 4 out-ch x 8 x-positions = 32 accumulators.
// STAGE 1: img -> g_f1 (CIN=32), STAGE 2: g_f1 -> g_f2 (CIN=64)
// ---------------------------------------------------------------------------
template<int CIN, int STAGE>
__global__ __launch_bounds__(256) void conv3d_relu_kernel(
    const float* __restrict__ img,
    const float* __restrict__ w,
    const float* __restrict__ bias)
{
    const float* in = (STAGE == 1) ? img : (const float*)g_f1;
    float* out      = (STAGE == 1) ? g_f1 : g_f2;

    extern __shared__ float sm[];
    float* in_s = sm;               // [CIN][6][6][10]
    float* w_s  = sm + CIN * 360;   // [64][27]

    const int tid = threadIdx.x;
    const int x0 = blockIdx.x * 8;
    const int y0 = blockIdx.y * 4;
    const int z0 = blockIdx.z * 4;

    // Load input tile with halo (zero padding at borders)
    const int total = CIN * 360;
    for (int i = tid; i < total; i += 256) {
        int c  = i / 360;
        int r  = i - c * 360;
        int zz = r / 60;
        int r2 = r - zz * 60;
        int yy = r2 / 10;
        int xx = r2 - yy * 10;
        int gz = z0 + zz - 1, gy = y0 + yy - 1, gx = x0 + xx - 1;
        float v = 0.f;
        if ((unsigned)gz < (unsigned)DIM && (unsigned)gy < (unsigned)DIM &&
            (unsigned)gx < (unsigned)DIM)
            v = in[c * D3 + gz * DD + gy * DIM + gx];
        in_s[i] = v;
    }

    const int og = tid >> 4;    // 0..15  -> out-channel group
    const int sg = tid & 15;    // 0..15  -> spatial group (z,y)
    const int ob = og * 4;
    const int lz = sg >> 2;     // 0..3
    const int ly = sg & 3;      // 0..3

    float acc[4][8];
    #pragma unroll
    for (int i = 0; i < 4; i++) {
        float b = bias[ob + i];
        #pragma unroll
        for (int j = 0; j < 8; j++) acc[i][j] = b;
    }

    for (int c = 0; c < CIN; c++) {
        __syncthreads();
        // stage weights for this input channel: [64 o][27 taps]
        for (int i = tid; i < 64 * 27; i += 256) {
            int o   = i / 27;
            int tap = i - o * 27;
            w_s[i] = w[(o * CIN + c) * 27 + tap];
        }
        __syncthreads();

        const float* cin_s = in_s + c * 360;
        #pragma unroll
        for (int kz = 0; kz < 3; kz++) {
            #pragma unroll
            for (int ky = 0; ky < 3; ky++) {
                const float* irow = cin_s + (lz + kz) * 60 + (ly + ky) * 10;
                float xr[10];
                #pragma unroll
                for (int u = 0; u < 10; u++) xr[u] = irow[u];
                const float* wp = w_s + ob * 27 + kz * 9 + ky * 3;
                #pragma unroll
                for (int i = 0; i < 4; i++) {
                    float w0 = wp[i * 27 + 0];
                    float w1 = wp[i * 27 + 1];
                    float w2 = wp[i * 27 + 2];
                    #pragma unroll
                    for (int j = 0; j < 8; j++) {
                        acc[i][j] = fmaf(w0, xr[j],     acc[i][j]);
                        acc[i][j] = fmaf(w1, xr[j + 1], acc[i][j]);
                        acc[i][j] = fmaf(w2, xr[j + 2], acc[i][j]);
                    }
                }
            }
        }
    }

    const int gz = z0 + lz, gy = y0 + ly;
    #pragma unroll
    for (int i = 0; i < 4; i++) {
        float* orow = out + (ob + i) * D3 + gz * DD + gy * DIM + x0;
        #pragma unroll
        for (int j = 0; j < 8; j++)
            orow[j] = fmaxf(acc[i][j], 0.f);
    }
}

// ---------------------------------------------------------------------------
// Fused gather + 4-layer MLP. Block = 64 points, 256 threads.
// Shared layout (floats):
//   X   [64 c][64 pt]   @ 0      (4096)   -- reused as H3 [64 o][64 pt]
//   H1  [256 o][64 pt]  @ 4096   (16384)
//   H2  [256 o][64 pt]  @ 20480  (16384)
//   Wb  [256 o][33]     @ 36864  (8448)   -- stride 33 kills bank conflicts
//   vox [64] int        @ 45312
// ---------------------------------------------------------------------------
#define SM_X   0
#define SM_H1  4096
#define SM_H2  20480
#define SM_WB  36864
#define SM_VOX 45312
#define SM_MLP_FLOATS (45312 + 64)

// COUT = 256 layer: thread = 4 o x 16 pts
__device__ __forceinline__ void mlp_layer_w256(
    const float* __restrict__ in_s, int cin,
    const float* __restrict__ W, const float* __restrict__ bias,
    float* __restrict__ out_s, float* __restrict__ wbuf,
    bool relu, int tid)
{
    const int og = tid >> 2, pg = tid & 3;
    const int ob = og * 4, pb = pg * 16;

    float acc[4][16];
    #pragma unroll
    for (int i = 0; i < 4; i++) {
        float b = bias[ob + i];
        #pragma unroll
        for (int j = 0; j < 16; j++) acc[i][j] = b;
    }

    for (int cb = 0; cb < cin; cb += 32) {
        __syncthreads();
        for (int i2 = tid; i2 < 256 * 32; i2 += 256) {
            int o = i2 >> 5, cc = i2 & 31;
            wbuf[o * 33 + cc] = W[o * cin + cb + cc];
        }
        __syncthreads();
        #pragma unroll 4
        for (int cc = 0; cc < 32; cc++) {
            const float4* xp = (const float4*)(in_s + (cb + cc) * 64 + pb);
            float4 xa = xp[0], xb = xp[1], xc = xp[2], xd = xp[3];
            float xv[16] = {xa.x, xa.y, xa.z, xa.w, xb.x, xb.y, xb.z, xb.w,
                            xc.x, xc.y, xc.z, xc.w, xd.x, xd.y, xd.z, xd.w};
            #pragma unroll
            for (int i = 0; i < 4; i++) {
                float wv = wbuf[(ob + i) * 33 + cc];
                #pragma unroll
                for (int j = 0; j < 16; j++)
                    acc[i][j] = fmaf(wv, xv[j], acc[i][j]);
            }
        }
    }
    __syncthreads();
    #pragma unroll
    for (int i = 0; i < 4; i++)
        #pragma unroll
        for (int j = 0; j < 16; j++) {
            float v = acc[i][j];
            out_s[(ob + i) * 64 + pb + j] = relu ? fmaxf(v, 0.f) : v;
        }
    __syncthreads();
}

// COUT = 64 layer (no relu): thread = 1 o x 16 pts
__device__ __forceinline__ void mlp_layer_w64(
    const float* __restrict__ in_s, int cin,
    const float* __restrict__ W, const float* __restrict__ bias,
    float* __restrict__ out_s, float* __restrict__ wbuf, int tid)
{
    const int o = tid & 63, pg = tid >> 6;
    const int pb = pg * 16;

    float acc[16];
    {
        float b = bias[o];
        #pragma unroll
        for (int j = 0; j < 16; j++) acc[j] = b;
    }

    for (int cb = 0; cb < cin; cb += 32) {
        __syncthreads();
        for (int i2 = tid; i2 < 64 * 32; i2 += 256) {
            int oo = i2 >> 5, cc = i2 & 31;
            wbuf[oo * 33 + cc] = W[oo * cin + cb + cc];
        }
        __syncthreads();
        #pragma unroll 4
        for (int cc = 0; cc < 32; cc++) {
            const float4* xp = (const float4*)(in_s + (cb + cc) * 64 + pb);
            float4 xa = xp[0], xb = xp[1], xc = xp[2], xd = xp[3];
            float xv[16] = {xa.x, xa.y, xa.z, xa.w, xb.x, xb.y, xb.z, xb.w,
                            xc.x, xc.y, xc.z, xc.w, xd.x, xd.y, xd.z, xd.w};
            float wv = wbuf[o * 33 + cc];
            #pragma unroll
            for (int j = 0; j < 16; j++)
                acc[j] = fmaf(wv, xv[j], acc[j]);
        }
    }
    __syncthreads();
    #pragma unroll
    for (int j = 0; j < 16; j++)
        out_s[o * 64 + pb + j] = acc[j];
    __syncthreads();
}

__global__ __launch_bounds__(256) void gather_mlp_kernel(
    const int* __restrict__ c0, const int* __restrict__ c1,
    const int* __restrict__ c2,
    const float* __restrict__ w1, const float* __restrict__ b1,
    const float* __restrict__ w2, const float* __restrict__ b2,
    const float* __restrict__ w3, const float* __restrict__ b3,
    const float* __restrict__ w4, const float* __restrict__ b4,
    float* __restrict__ out)
{
    extern __shared__ float sm[];
    float* X   = sm + SM_X;
    float* H1  = sm + SM_H1;
    float* H2  = sm + SM_H2;
    float* Wb  = sm + SM_WB;
    int*   vox = (int*)(sm + SM_VOX);

    const int tid = threadIdx.x;
    const int n0  = blockIdx.x * 64;

    if (tid < 64) {
        int n = n0 + tid;
        vox[tid] = c0[n] * DD + c1[n] * DIM + c2[n];
    }
    __syncthreads();

    // Gather: X[c][pt] = f2[c][vox[pt]]
    const float* f2 = (const float*)g_f2;
    for (int i = tid; i < 64 * 64; i += 256) {
        int c = i >> 6, n = i & 63;
        X[i] = f2[c * D3 + vox[n]];
    }
    __syncthreads();

    mlp_layer_w256(X,  64,  w1, b1, H1, Wb, true, tid);   // 64 -> 256, relu
    mlp_layer_w256(H1, 256, w2, b2, H2, Wb, true, tid);   // 256 -> 256, relu
    mlp_layer_w64 (H2, 256, w3, b3, X,  Wb, tid);         // 256 -> 64, no relu

    // Layer 4: 64 -> 6, write to global out[o*N + n]
    for (int i = tid; i < 6 * 64; i += 256) {
        int o = i >> 6, n = i & 63;
        float a = b4[o];
        #pragma unroll
        for (int c = 0; c < 64; c++)
            a = fmaf(w4[o * 64 + c], X[c * 64 + n], a);
        out[o * NPTS + n0 + n] = a;
    }
}

// ---------------------------------------------------------------------------
extern "C" void kernel_launch(void* const* d_in, const int* in_sizes, int n_in,
                              void* d_out, int out_size)
{
    const float* img = (const float*)d_in[0];
    const int*   c0  = (const int*)d_in[1];
    const int*   c1  = (const int*)d_in[2];
    const int*   c2  = (const int*)d_in[3];
    const float* we1 = (const float*)d_in[4];
    const float* be1 = (const float*)d_in[5];
    const float* we2 = (const float*)d_in[6];
    const float* be2 = (const float*)d_in[7];
    const float* wp1 = (const float*)d_in[8];
    const float* bp1 = (const float*)d_in[9];
    const float* wp2 = (const float*)d_in[10];
    const float* bp2 = (const float*)d_in[11];
    const float* wp3 = (const float*)d_in[12];
    const float* bp3 = (const float*)d_in[13];
    const float* wp4 = (const float*)d_in[14];
    const float* bp4 = (const float*)d_in[15];
    float* out = (float*)d_out;

    const int smem1 = (32 * 360 + 64 * 27) * 4;   // 52,992 B
    const int smem2 = (64 * 360 + 64 * 27) * 4;   // 99,072 B
    const int smemM = SM_MLP_FLOATS * 4;          // 181,504 B

    cudaFuncSetAttribute(conv3d_relu_kernel<32, 1>,
                         cudaFuncAttributeMaxDynamicSharedMemorySize, smem1);
    cudaFuncSetAttribute(conv3d_relu_kernel<64, 2>,
                         cudaFuncAttributeMaxDynamicSharedMemorySize, smem2);
    cudaFuncSetAttribute(gather_mlp_kernel,
                         cudaFuncAttributeMaxDynamicSharedMemorySize, smemM);

    dim3 cgrid(DIM / 8, DIM / 4, DIM / 4);   // (10, 20, 20)
    conv3d_relu_kernel<32, 1><<<cgrid, 256, smem1>>>(img, we1, be1);
    conv3d_relu_kernel<64, 2><<<cgrid, 256, smem2>>>(img, we2, be2);
    gather_mlp_kernel<<<NPTS / 64, 256, smemM>>>(c0, c1, c2,
                                                 wp1, bp1, wp2, bp2,
                                                 wp3, bp3, wp4, bp4, out);
}

// round 2
// speedup vs baseline: 1.2265x; 1.2265x over previous
#include <cuda_runtime.h>

#define DIM 80
#define DD 6400
#define D3 512000
#define NPTS 200000

// Scratch (device globals — no allocation in kernel_launch)
__device__ float g_f1[64 * D3];
__device__ float g_f2[64 * D3];
__device__ float g_wT1[32 * 27 * 64];   // [c][tap][o]
__device__ float g_wT2[64 * 27 * 64];

typedef unsigned long long u64;

__device__ __forceinline__ u64 pack2(float lo, float hi) {
    u64 r; asm("mov.b64 %0, {%1, %2};" : "=l"(r) : "f"(lo), "f"(hi)); return r;
}
__device__ __forceinline__ u64 bcast2(float v) { return pack2(v, v); }
__device__ __forceinline__ float2 unpack2(u64 p) {
    float2 f; asm("mov.b64 {%0, %1}, %2;" : "=f"(f.x), "=f"(f.y) : "l"(p)); return f;
}
__device__ __forceinline__ u64 fma2(u64 a, u64 b, u64 c) {
    u64 d; asm("fma.rn.f32x2 %0, %1, %2, %3;" : "=l"(d) : "l"(a), "l"(b), "l"(c));
    return d;
}

// ---------------------------------------------------------------------------
// One-time weight transpose: w[o][c][27] -> wT[c][tap][o]
// ---------------------------------------------------------------------------
template<int CIN>
__global__ void transpose_w_kernel(const float* __restrict__ w,
                                   float* __restrict__ wT)
{
    int idx = blockIdx.x * 256 + threadIdx.x;
    if (idx >= 64 * CIN * 27) return;
    int o = idx & 63;
    int r = idx >> 6;
    int tap = r % 27;
    int c = r / 27;
    wT[idx] = w[(o * CIN + c) * 27 + tap];
}

// ---------------------------------------------------------------------------
// 3D conv 3x3x3 pad 1 + bias + ReLU, FFMA2 (f32x2) packed over out-ch pairs.
// Block: 64 out-ch x (4z,4y,8x). Thread: 4 o x 8 x = 2 o-pairs x 8.
// Input channels processed in chunks of 8 (input tile + weights staged/chunk).
// ---------------------------------------------------------------------------
template<int CIN, int STAGE>
__global__ __launch_bounds__(256) void conv3d_relu_kernel(
    const float* __restrict__ img,
    const float* __restrict__ bias)
{
    const float* in = (STAGE == 1) ? img : (const float*)g_f1;
    float* out      = (STAGE == 1) ? g_f1 : g_f2;
    const float* wT = (STAGE == 1) ? (const float*)g_wT1 : (const float*)g_wT2;

    extern __shared__ float sm[];
    float* in_s = sm;              // [8][6][6][10] = 2880 floats
    float* w_s  = sm + 8 * 360;    // [8][27][64]   = 13824 floats

    const int tid = threadIdx.x;
    const int x0 = blockIdx.x * 8;
    const int y0 = blockIdx.y * 4;
    const int z0 = blockIdx.z * 4;

    const int og = tid >> 4;    // 0..15
    const int sg = tid & 15;
    const int ob = og * 4;
    const int lz = sg >> 2;
    const int ly = sg & 3;

    u64 acc[2][8];
    #pragma unroll
    for (int ip = 0; ip < 2; ip++) {
        u64 b2 = pack2(bias[ob + 2 * ip], bias[ob + 2 * ip + 1]);
        #pragma unroll
        for (int j = 0; j < 8; j++) acc[ip][j] = b2;
    }

    for (int cb = 0; cb < CIN; cb += 8) {
        __syncthreads();
        // stage 8 input channels (with halo, zero pad)
        for (int i = tid; i < 8 * 360; i += 256) {
            int c  = i / 360;
            int r  = i - c * 360;
            int zz = r / 60;
            int r2 = r - zz * 60;
            int yy = r2 / 10;
            int xx = r2 - yy * 10;
            int gz = z0 + zz - 1, gy = y0 + yy - 1, gx = x0 + xx - 1;
            float v = 0.f;
            if ((unsigned)gz < (unsigned)DIM && (unsigned)gy < (unsigned)DIM &&
                (unsigned)gx < (unsigned)DIM)
                v = in[(cb + c) * D3 + gz * DD + gy * DIM + gx];
            in_s[i] = v;
        }
        // stage 8 channels of weights (coalesced linear copy)
        {
            const float4* wsrc = (const float4*)(wT + cb * 27 * 64);
            float4* wdst = (float4*)w_s;
            for (int i = tid; i < 8 * 27 * 16; i += 256)
                wdst[i] = wsrc[i];
        }
        __syncthreads();

        for (int c8 = 0; c8 < 8; c8++) {
            const float* cin_s = in_s + c8 * 360;
            const float* wc    = w_s + c8 * 27 * 64;
            #pragma unroll
            for (int kz = 0; kz < 3; kz++) {
                #pragma unroll
                for (int ky = 0; ky < 3; ky++) {
                    const float* irow = cin_s + (lz + kz) * 60 + (ly + ky) * 10;
                    u64 xb[10];
                    #pragma unroll
                    for (int u = 0; u < 10; u++) xb[u] = bcast2(irow[u]);
                    const float* wrow = wc + (kz * 9 + ky * 3) * 64;
                    #pragma unroll
                    for (int ip = 0; ip < 2; ip++) {
                        u64 w0 = *(const u64*)(wrow +       ob + 2 * ip);
                        u64 w1 = *(const u64*)(wrow +  64 + ob + 2 * ip);
                        u64 w2 = *(const u64*)(wrow + 128 + ob + 2 * ip);
                        #pragma unroll
                        for (int j = 0; j < 8; j++) {
                            acc[ip][j] = fma2(w0, xb[j],     acc[ip][j]);
                            acc[ip][j] = fma2(w1, xb[j + 1], acc[ip][j]);
                            acc[ip][j] = fma2(w2, xb[j + 2], acc[ip][j]);
                        }
                    }
                }
            }
        }
    }

    const int gz = z0 + lz, gy = y0 + ly;
    #pragma unroll
    for (int ip = 0; ip < 2; ip++) {
        float* r0 = out + (ob + 2 * ip) * D3 + gz * DD + gy * DIM + x0;
        float* r1 = r0 + D3;
        #pragma unroll
        for (int j = 0; j < 8; j++) {
            float2 v = unpack2(acc[ip][j]);
            r0[j] = fmaxf(v.x, 0.f);
            r1[j] = fmaxf(v.y, 0.f);
        }
    }
}

// ---------------------------------------------------------------------------
// Fused gather + 4-layer MLP, 512 threads, FFMA2 packed over point pairs.
// Shared (floats): X[64][64]@0  H1[256][64]@4096  H2[256][64]@20480
//                  Wb[256][33]@36864  vox[64]@45312
// ---------------------------------------------------------------------------
#define SM_X   0
#define SM_H1  4096
#define SM_H2  20480
#define SM_WB  36864
#define SM_VOX 45312
#define SM_MLP_FLOATS (45312 + 64)
#define MT 512

// 256-wide layer: thread = 2 out x 16 pts (8 point-pairs)
__device__ __forceinline__ void mlp_layer_w256(
    const float* __restrict__ in_s, int cin,
    const float* __restrict__ W, const float* __restrict__ bias,
    float* __restrict__ out_s, float* __restrict__ wbuf,
    bool relu, int tid)
{
    const int og = tid >> 2, pg = tid & 3;
    const int ob = og * 2, pb = pg * 16;

    u64 acc[2][8];
    #pragma unroll
    for (int i = 0; i < 2; i++) {
        u64 b2 = bcast2(bias[ob + i]);
        #pragma unroll
        for (int jj = 0; jj < 8; jj++) acc[i][jj] = b2;
    }

    for (int cb = 0; cb < cin; cb += 32) {
        __syncthreads();
        for (int i2 = tid; i2 < 256 * 32; i2 += MT) {
            int o = i2 >> 5, cc = i2 & 31;
            wbuf[o * 33 + cc] = W[o * cin + cb + cc];
        }
        __syncthreads();
        #pragma unroll 4
        for (int cc = 0; cc < 32; cc++) {
            const ulonglong2* xq =
                (const ulonglong2*)(in_s + (cb + cc) * 64 + pb);
            ulonglong2 q0 = xq[0], q1 = xq[1], q2 = xq[2], q3 = xq[3];
            #pragma unroll
            for (int i = 0; i < 2; i++) {
                u64 wv = bcast2(wbuf[(ob + i) * 33 + cc]);
                acc[i][0] = fma2(wv, q0.x, acc[i][0]);
                acc[i][1] = fma2(wv, q0.y, acc[i][1]);
                acc[i][2] = fma2(wv, q1.x, acc[i][2]);
                acc[i][3] = fma2(wv, q1.y, acc[i][3]);
                acc[i][4] = fma2(wv, q2.x, acc[i][4]);
                acc[i][5] = fma2(wv, q2.y, acc[i][5]);
                acc[i][6] = fma2(wv, q3.x, acc[i][6]);
                acc[i][7] = fma2(wv, q3.y, acc[i][7]);
            }
        }
    }
    __syncthreads();
    #pragma unroll
    for (int i = 0; i < 2; i++)
        #pragma unroll
        for (int jj = 0; jj < 8; jj++) {
            float2 v = unpack2(acc[i][jj]);
            if (relu) { v.x = fmaxf(v.x, 0.f); v.y = fmaxf(v.y, 0.f); }
            *(float2*)(out_s + (ob + i) * 64 + pb + 2 * jj) = v;
        }
    __syncthreads();
}

// 64-wide layer (no relu): thread = 1 out x 8 pts (4 point-pairs)
__device__ __forceinline__ void mlp_layer_w64(
    const float* __restrict__ in_s, int cin,
    const float* __restrict__ W, const float* __restrict__ bias,
    float* __restrict__ out_s, float* __restrict__ wbuf, int tid)
{
    const int o = tid & 63, pg = tid >> 6;
    const int pb = pg * 8;

    u64 acc[4];
    {
        u64 b2 = bcast2(bias[o]);
        #pragma unroll
        for (int jj = 0; jj < 4; jj++) acc[jj] = b2;
    }

    for (int cb = 0; cb < cin; cb += 32) {
        __syncthreads();
        for (int i2 = tid; i2 < 64 * 32; i2 += MT) {
            int oo = i2 >> 5, cc = i2 & 31;
            wbuf[oo * 33 + cc] = W[oo * cin + cb + cc];
        }
        __syncthreads();
        #pragma unroll 4
        for (int cc = 0; cc < 32; cc++) {
            const ulonglong2* xq =
                (const ulonglong2*)(in_s + (cb + cc) * 64 + pb);
            ulonglong2 q0 = xq[0], q1 = xq[1];
            u64 wv = bcast2(wbuf[o * 33 + cc]);
            acc[0] = fma2(wv, q0.x, acc[0]);
            acc[1] = fma2(wv, q0.y, acc[1]);
            acc[2] = fma2(wv, q1.x, acc[2]);
            acc[3] = fma2(wv, q1.y, acc[3]);
        }
    }
    __syncthreads();
    #pragma unroll
    for (int jj = 0; jj < 4; jj++) {
        float2 v = unpack2(acc[jj]);
        *(float2*)(out_s + o * 64 + pb + 2 * jj) = v;
    }
    __syncthreads();
}

__global__ __launch_bounds__(MT) void gather_mlp_kernel(
    const int* __restrict__ c0, const int* __restrict__ c1,
    const int* __restrict__ c2,
    const float* __restrict__ w1, const float* __restrict__ b1,
    const float* __restrict__ w2, const float* __restrict__ b2,
    const float* __restrict__ w3, const float* __restrict__ b3,
    const float* __restrict__ w4, const float* __restrict__ b4,
    float* __restrict__ out)
{
    extern __shared__ float sm[];
    float* X   = sm + SM_X;
    float* H1  = sm + SM_H1;
    float* H2  = sm + SM_H2;
    float* Wb  = sm + SM_WB;
    int*   vox = (int*)(sm + SM_VOX);

    const int tid = threadIdx.x;
    const int n0  = blockIdx.x * 64;

    if (tid < 64) {
        int n = n0 + tid;
        vox[tid] = c0[n] * DD + c1[n] * DIM + c2[n];
    }
    __syncthreads();

    const float* f2 = (const float*)g_f2;
    for (int i = tid; i < 64 * 64; i += MT) {
        int c = i >> 6, n = i & 63;
        X[i] = f2[c * D3 + vox[n]];
    }
    __syncthreads();

    mlp_layer_w256(X,  64,  w1, b1, H1, Wb, true, tid);
    mlp_layer_w256(H1, 256, w2, b2, H2, Wb, true, tid);
    mlp_layer_w64 (H2, 256, w3, b3, X,  Wb, tid);

    if (tid < 384) {
        int o = tid >> 6, n = tid & 63;
        float a = b4[o];
        #pragma unroll
        for (int c = 0; c < 64; c++)
            a = fmaf(w4[o * 64 + c], X[c * 64 + n], a);
        out[o * NPTS + n0 + n] = a;
    }
}

// ---------------------------------------------------------------------------
extern "C" void kernel_launch(void* const* d_in, const int* in_sizes, int n_in,
                              void* d_out, int out_size)
{
    const float* img = (const float*)d_in[0];
    const int*   c0  = (const int*)d_in[1];
    const int*   c1  = (const int*)d_in[2];
    const int*   c2  = (const int*)d_in[3];
    const float* we1 = (const float*)d_in[4];
    const float* be1 = (const float*)d_in[5];
    const float* we2 = (const float*)d_in[6];
    const float* be2 = (const float*)d_in[7];
    const float* wp1 = (const float*)d_in[8];
    const float* bp1 = (const float*)d_in[9];
    const float* wp2 = (const float*)d_in[10];
    const float* bp2 = (const float*)d_in[11];
    const float* wp3 = (const float*)d_in[12];
    const float* bp3 = (const float*)d_in[13];
    const float* wp4 = (const float*)d_in[14];
    const float* bp4 = (const float*)d_in[15];
    float* out = (float*)d_out;

    const int smemC = (8 * 360 + 8 * 27 * 64) * 4;   // 66,816 B
    const int smemM = SM_MLP_FLOATS * 4;             // 181,504 B

    cudaFuncSetAttribute(conv3d_relu_kernel<32, 1>,
                         cudaFuncAttributeMaxDynamicSharedMemorySize, smemC);
    cudaFuncSetAttribute(conv3d_relu_kernel<64, 2>,
                         cudaFuncAttributeMaxDynamicSharedMemorySize, smemC);
    cudaFuncSetAttribute(gather_mlp_kernel,
                         cudaFuncAttributeMaxDynamicSharedMemorySize, smemM);

    float* wT1;  cudaGetSymbolAddress((void**)&wT1, g_wT1);
    float* wT2;  cudaGetSymbolAddress((void**)&wT2, g_wT2);

    transpose_w_kernel<32><<<(64 * 32 * 27 + 255) / 256, 256>>>(we1, wT1);
    transpose_w_kernel<64><<<(64 * 64 * 27 + 255) / 256, 256>>>(we2, wT2);

    dim3 cgrid(DIM / 8, DIM / 4, DIM / 4);   // (10, 20, 20)
    conv3d_relu_kernel<32, 1><<<cgrid, 256, smemC>>>(img, be1);
    conv3d_relu_kernel<64, 2><<<cgrid, 256, smemC>>>(img, be2);
    gather_mlp_kernel<<<NPTS / 64, MT, smemM>>>(c0, c1, c2,
                                                wp1, bp1, wp2, bp2,
                                                wp3, bp3, wp4, bp4, out);
}